// round 2
// baseline (speedup 1.0000x reference)
#include <cuda_runtime.h>
#include <math.h>

#define IN_DIM 128
#define EMB    128
#define HID    64
#define NEG    0.2f
#define MAXN   10048

// ---------------- scratch (static device globals; no allocation) ------------
__device__ float g_z[MAXN * HID];      // z = h @ gat_w
__device__ float g_S[MAXN * HID];      // unnormalized segment sum of ex * z[src]
__device__ float g_embed[MAXN * HID];  // final embed_x
__device__ float g_asrc[MAXN];
__device__ float g_adst[MAXN];
__device__ int   g_menc[MAXN];         // ordered-int encoded segment max
__device__ float g_den[MAXN];          // segment sum of ex
__device__ int   g_is64;               // 1 if edge_index is int64, 0 if int32

// ordered-int encoding of float for atomicMax
__device__ __forceinline__ int fenc(float f) {
    int b = __float_as_int(f);
    return b >= 0 ? b : (b ^ 0x7fffffff);
}
__device__ __forceinline__ float fdec(int e) {
    return __int_as_float(e >= 0 ? e : (e ^ 0x7fffffff));
}

__device__ __forceinline__ float sigm(float v) {
    return __fdividef(1.0f, 1.0f + __expf(-v));
}

// fetch (src,dst) for flattened edge id i, handling int32/int64 layouts
__device__ __forceinline__ void edge_pair(const void* ei, int E, int N, int i,
                                          int& s, int& d)
{
    if (i >= E) { s = d = i - E; return; }   // self loop
    if (g_is64) {
        const long long* p = (const long long*)ei;
        s = (int)p[i];
        d = (int)p[E + i];
    } else {
        const int* p = (const int*)ei;
        s = p[i];
        d = p[E + i];
    }
}

// ---------------- dtype detector -------------------------------------------
__global__ void detect_dtype(const void* ei, int N) {
    // Read first 32 values as int64. Genuine int64 indices are all in [0,N).
    // int32 data reinterpreted as int64 yields huge values (hi word = another
    // random index, nonzero w.h.p.).
    const long long* p = (const long long*)ei;
    int ok = 1;
    #pragma unroll
    for (int i = 0; i < 32; i++) {
        long long v = p[i];
        if (v < 0 || v >= (long long)N) ok = 0;
    }
    g_is64 = ok;
}

// ---------------- init ------------------------------------------------------
__global__ void init_scratch(int N) {
    int i = blockIdx.x * blockDim.x + threadIdx.x;
    if (i < N * HID) g_S[i] = 0.0f;
    if (i < N) {
        g_den[i]  = 0.0f;
        g_menc[i] = (int)0x80000000;   // below any encoded float
    }
}

// ---------------- fused node forward: h=relu(xW1+b1); z=hW2; a_src/a_dst ----
__global__ __launch_bounds__(256) void node_fwd(
    const float* __restrict__ x, const float* __restrict__ W1,
    const float* __restrict__ b1, const float* __restrict__ W2,
    const float* __restrict__ att_s, const float* __restrict__ att_d, int N)
{
    __shared__ float xs[32][IN_DIM];
    __shared__ float hs[32][EMB];
    __shared__ float zs[32][HID];
    const int tid = threadIdx.x;
    const int r0  = blockIdx.x * 32;

    for (int i = tid; i < 32 * IN_DIM; i += 256) {
        int r = i / IN_DIM, c = i % IN_DIM;
        xs[r][c] = (r0 + r < N) ? x[(size_t)(r0 + r) * IN_DIM + c] : 0.0f;
    }
    __syncthreads();

    // GEMM1: 32x128, 16 outputs/thread
    {
        int col = tid & 127;
        int rg  = tid >> 7;           // 0..1
        float acc[16];
        #pragma unroll
        for (int j = 0; j < 16; j++) acc[j] = 0.0f;
        for (int k = 0; k < IN_DIM; k++) {
            float w = W1[k * EMB + col];
            #pragma unroll
            for (int j = 0; j < 16; j++) acc[j] += xs[rg + 2 * j][k] * w;
        }
        float bb = b1[col];
        #pragma unroll
        for (int j = 0; j < 16; j++)
            hs[rg + 2 * j][col] = fmaxf(acc[j] + bb, 0.0f);
    }
    __syncthreads();

    // GEMM2: 32x64, 8 outputs/thread
    {
        int col = tid & 63;
        int rg  = tid >> 6;           // 0..3
        float acc[8];
        #pragma unroll
        for (int j = 0; j < 8; j++) acc[j] = 0.0f;
        for (int k = 0; k < EMB; k++) {
            float w = W2[k * HID + col];
            #pragma unroll
            for (int j = 0; j < 8; j++) acc[j] += hs[rg + 4 * j][k] * w;
        }
        #pragma unroll
        for (int j = 0; j < 8; j++) {
            int r = rg + 4 * j;
            zs[r][col] = acc[j];
            if (r0 + r < N) g_z[(size_t)(r0 + r) * HID + col] = acc[j];
        }
    }
    __syncthreads();

    if (tid < 32) {
        int r = tid;
        if (r0 + r < N) {
            float s1 = 0.0f, s2 = 0.0f;
            #pragma unroll
            for (int k = 0; k < HID; k++) {
                float zv = zs[r][k];
                s1 += zv * att_s[k];
                s2 += zv * att_d[k];
            }
            g_asrc[r0 + r] = s1;
            g_adst[r0 + r] = s2;
        }
    }
}

// ---------------- edge pass 1: segment max --------------------------------
__global__ void edge_max(const void* __restrict__ ei, int E, int N) {
    int i = blockIdx.x * blockDim.x + threadIdx.x;
    int ET = E + N;
    if (i >= ET) return;
    int s, d;
    edge_pair(ei, E, N, i, s, d);
    float e = g_asrc[s] + g_adst[d];
    e = e > 0.0f ? e : NEG * e;
    atomicMax(&g_menc[d], fenc(e));
}

// ---------------- edge pass 2: ex, denom, scatter ex*z[src] ----------------
__global__ __launch_bounds__(256) void edge_scatter(
    const void* __restrict__ ei, int E, int N)
{
    int warp = (blockIdx.x * blockDim.x + threadIdx.x) >> 5;
    int lane = threadIdx.x & 31;
    int ET = E + N;
    if (warp >= ET) return;
    int s, d;
    edge_pair(ei, E, N, warp, s, d);
    float e = g_asrc[s] + g_adst[d];
    e = e > 0.0f ? e : NEG * e;
    float ex = __expf(e - fdec(g_menc[d]));
    if (lane == 0) atomicAdd(&g_den[d], ex);
    const float* zr = g_z + (size_t)s * HID;
    float*       Sr = g_S + (size_t)d * HID;
    atomicAdd(Sr + lane,      ex * zr[lane]);
    atomicAdd(Sr + 32 + lane, ex * zr[32 + lane]);
}

// ---------------- normalize: embed = S/den + gat_b -------------------------
__global__ void normalize_embed(const float* __restrict__ gat_b, int N)
{
    int i = blockIdx.x * blockDim.x + threadIdx.x;
    if (i >= N * HID) return;
    int n = i >> 6, f = i & 63;
    g_embed[i] = g_S[i] / g_den[n] + gat_b[f];
}

// ---------------- copy embed into output tail ------------------------------
__global__ void copy_embed(float* __restrict__ out_embed, int N)
{
    int i = blockIdx.x * blockDim.x + threadIdx.x;
    if (i < N * HID) out_embed[i] = g_embed[i];
}

// ---------------- sim = sigmoid(Z @ Z^T) : 64x64 tiles, fp32 SIMT ----------
__global__ __launch_bounds__(256) void sim_gemm(
    float* __restrict__ out, int N)
{
    __shared__ float As[HID][68];   // [k][row], padded
    __shared__ float Bs[HID][68];
    const float* __restrict__ Z = g_embed;
    const int tid = threadIdx.x;
    const int i0 = blockIdx.y * 64;
    const int j0 = blockIdx.x * 64;

    {
        int r  = tid >> 4;          // 0..15
        int kq = tid & 15;          // k = kq*4
        #pragma unroll
        for (int rr = 0; rr < 4; rr++) {
            int row = r + rr * 16;
            float4 va = (i0 + row < N)
                ? *(const float4*)(Z + (size_t)(i0 + row) * HID + kq * 4)
                : make_float4(0, 0, 0, 0);
            As[kq * 4 + 0][row] = va.x;
            As[kq * 4 + 1][row] = va.y;
            As[kq * 4 + 2][row] = va.z;
            As[kq * 4 + 3][row] = va.w;
            float4 vb = (j0 + row < N)
                ? *(const float4*)(Z + (size_t)(j0 + row) * HID + kq * 4)
                : make_float4(0, 0, 0, 0);
            Bs[kq * 4 + 0][row] = vb.x;
            Bs[kq * 4 + 1][row] = vb.y;
            Bs[kq * 4 + 2][row] = vb.z;
            Bs[kq * 4 + 3][row] = vb.w;
        }
    }
    __syncthreads();

    const int tx = tid & 15, ty = tid >> 4;
    float acc[4][4];
    #pragma unroll
    for (int r = 0; r < 4; r++)
        #pragma unroll
        for (int c = 0; c < 4; c++) acc[r][c] = 0.0f;

    #pragma unroll 16
    for (int k = 0; k < HID; k++) {
        float4 a = *(const float4*)&As[k][ty * 4];
        float4 b = *(const float4*)&Bs[k][tx * 4];
        float av[4] = {a.x, a.y, a.z, a.w};
        float bv[4] = {b.x, b.y, b.z, b.w};
        #pragma unroll
        for (int r = 0; r < 4; r++)
            #pragma unroll
            for (int c = 0; c < 4; c++)
                acc[r][c] += av[r] * bv[c];
    }

    #pragma unroll
    for (int r = 0; r < 4; r++) {
        int gi = i0 + ty * 4 + r;
        if (gi >= N) continue;
        int gj = j0 + tx * 4;
        float4 o;
        o.x = sigm(acc[r][0]);
        o.y = sigm(acc[r][1]);
        o.z = sigm(acc[r][2]);
        o.w = sigm(acc[r][3]);
        float* orow = out + (size_t)gi * N + gj;
        if (gj + 3 < N) {
            *(float4*)orow = o;
        } else {
            if (gj + 0 < N) orow[0] = o.x;
            if (gj + 1 < N) orow[1] = o.y;
            if (gj + 2 < N) orow[2] = o.z;
            if (gj + 3 < N) orow[3] = o.w;
        }
    }
}

// ---------------- launch ----------------------------------------------------
extern "C" void kernel_launch(void* const* d_in, const int* in_sizes, int n_in,
                              void* d_out, int out_size)
{
    const float* x    = (const float*)d_in[0];
    const void*  ei   = d_in[1];
    const float* W1   = (const float*)d_in[2];
    const float* b1   = (const float*)d_in[3];
    const float* W2   = (const float*)d_in[4];
    const float* atts = (const float*)d_in[5];
    const float* attd = (const float*)d_in[6];
    const float* gb   = (const float*)d_in[7];

    const int N = in_sizes[0] / IN_DIM;
    const int E = in_sizes[1] / 2;
    const int ET = E + N;

    float* out = (float*)d_out;

    detect_dtype<<<1, 1>>>(ei, N);
    init_scratch<<<(N * HID + 255) / 256, 256>>>(N);
    node_fwd<<<(N + 31) / 32, 256>>>(x, W1, b1, W2, atts, attd, N);
    edge_max<<<(ET + 255) / 256, 256>>>(ei, E, N);
    edge_scatter<<<(ET * 32 + 255) / 256, 256>>>(ei, E, N);
    normalize_embed<<<(N * HID + 255) / 256, 256>>>(gb, N);

    // embed_x output tail (only if the output buffer has room for it)
    if ((size_t)out_size >= (size_t)N * N + (size_t)N * HID) {
        copy_embed<<<(N * HID + 255) / 256, 256>>>(out + (size_t)N * N, N);
    }

    dim3 grid((N + 63) / 64, (N + 63) / 64);
    sim_gemm<<<grid, 256>>>(out, N);
}

// round 4
// speedup vs baseline: 1.6766x; 1.6766x over previous
#include <cuda_runtime.h>
#include <math.h>
#include <stdint.h>

#define IN_DIM 128
#define EMB    128
#define HID    64
#define NEG    0.2f
#define MAXN   10240   // padded to tile multiple

typedef unsigned long long ULL;

// ---------------- scratch (static device globals; no allocation) ------------
__device__ float g_z[MAXN * HID];
__device__ float g_S[MAXN * HID];
__device__ float g_embed[MAXN * HID];   // zero-padded to MAXN rows
__device__ float g_asrc[MAXN];
__device__ float g_adst[MAXN];
__device__ int   g_menc[MAXN];
__device__ float g_den[MAXN];
__device__ int   g_is64;

// ---------------- small helpers ---------------------------------------------
__device__ __forceinline__ int fenc(float f) {
    int b = __float_as_int(f);
    return b >= 0 ? b : (b ^ 0x7fffffff);
}
__device__ __forceinline__ float fdec(int e) {
    return __int_as_float(e >= 0 ? e : (e ^ 0x7fffffff));
}
__device__ __forceinline__ float sigm(float v) {
    return __fdividef(1.0f, 1.0f + __expf(-v));
}
__device__ __forceinline__ void edge_pair(const void* ei, int E, int N, int i,
                                          int& s, int& d)
{
    if (i >= E) { s = d = i - E; return; }
    if (g_is64) {
        const long long* p = (const long long*)ei;
        s = (int)p[i]; d = (int)p[E + i];
    } else {
        const int* p = (const int*)ei;
        s = p[i]; d = p[E + i];
    }
}

// packed f32x2 helpers
#define PACK_BCAST(out, f) \
    asm("mov.b64 %0, {%1, %1};" : "=l"(out) : "r"(__float_as_uint(f)))
#define FMA2(d, a, b) \
    asm("fma.rn.f32x2 %0, %1, %2, %0;" : "+l"(d) : "l"(a), "l"(b))
__device__ __forceinline__ float2 unpk(ULL v) {
    float2 r;
    asm("mov.b64 {%0, %1}, %2;" : "=f"(r.x), "=f"(r.y) : "l"(v));
    return r;
}

// ---------------- dtype detector --------------------------------------------
__global__ void detect_dtype(const void* ei, int N) {
    const long long* p = (const long long*)ei;
    int ok = 1;
    #pragma unroll
    for (int i = 0; i < 32; i++) {
        long long v = p[i];
        if (v < 0 || v >= (long long)N) ok = 0;
    }
    g_is64 = ok;
}

// ---------------- init --------------------------------------------------------
__global__ void init_scratch(int N) {
    int i = blockIdx.x * blockDim.x + threadIdx.x;
    if (i < N * HID) g_S[i] = 0.0f;
    if (i < N) {
        g_den[i]  = 0.0f;
        g_menc[i] = (int)0x80000000;
    }
}

// ---------------- fused node forward -----------------------------------------
__global__ __launch_bounds__(256) void node_fwd(
    const float* __restrict__ x, const float* __restrict__ W1,
    const float* __restrict__ b1, const float* __restrict__ W2,
    const float* __restrict__ att_s, const float* __restrict__ att_d, int N)
{
    __shared__ float xs[32][IN_DIM];
    __shared__ float hs[32][EMB];
    __shared__ float zs[32][HID];
    const int tid = threadIdx.x;
    const int r0  = blockIdx.x * 32;

    for (int i = tid; i < 32 * IN_DIM; i += 256) {
        int r = i / IN_DIM, c = i % IN_DIM;
        xs[r][c] = (r0 + r < N) ? x[(size_t)(r0 + r) * IN_DIM + c] : 0.0f;
    }
    __syncthreads();

    {
        int col = tid & 127;
        int rg  = tid >> 7;
        float acc[16];
        #pragma unroll
        for (int j = 0; j < 16; j++) acc[j] = 0.0f;
        for (int k = 0; k < IN_DIM; k++) {
            float w = W1[k * EMB + col];
            #pragma unroll
            for (int j = 0; j < 16; j++) acc[j] += xs[rg + 2 * j][k] * w;
        }
        float bb = b1[col];
        #pragma unroll
        for (int j = 0; j < 16; j++)
            hs[rg + 2 * j][col] = fmaxf(acc[j] + bb, 0.0f);
    }
    __syncthreads();

    {
        int col = tid & 63;
        int rg  = tid >> 6;
        float acc[8];
        #pragma unroll
        for (int j = 0; j < 8; j++) acc[j] = 0.0f;
        for (int k = 0; k < EMB; k++) {
            float w = W2[k * HID + col];
            #pragma unroll
            for (int j = 0; j < 8; j++) acc[j] += hs[rg + 4 * j][k] * w;
        }
        #pragma unroll
        for (int j = 0; j < 8; j++) {
            int r = rg + 4 * j;
            zs[r][col] = acc[j];
            if (r0 + r < N) g_z[(size_t)(r0 + r) * HID + col] = acc[j];
        }
    }
    __syncthreads();

    if (tid < 32) {
        int r = tid;
        if (r0 + r < N) {
            float s1 = 0.0f, s2 = 0.0f;
            #pragma unroll
            for (int k = 0; k < HID; k++) {
                float zv = zs[r][k];
                s1 += zv * att_s[k];
                s2 += zv * att_d[k];
            }
            g_asrc[r0 + r] = s1;
            g_adst[r0 + r] = s2;
        }
    }
}

// ---------------- edge pass 1: segment max ------------------------------------
__global__ void edge_max(const void* __restrict__ ei, int E, int N) {
    int i = blockIdx.x * blockDim.x + threadIdx.x;
    int ET = E + N;
    if (i >= ET) return;
    int s, d;
    edge_pair(ei, E, N, i, s, d);
    float e = g_asrc[s] + g_adst[d];
    e = e > 0.0f ? e : NEG * e;
    atomicMax(&g_menc[d], fenc(e));
}

// ---------------- edge pass 2: scatter ----------------------------------------
__global__ __launch_bounds__(256) void edge_scatter(
    const void* __restrict__ ei, int E, int N)
{
    int warp = (blockIdx.x * blockDim.x + threadIdx.x) >> 5;
    int lane = threadIdx.x & 31;
    int ET = E + N;
    if (warp >= ET) return;
    int s, d;
    edge_pair(ei, E, N, warp, s, d);
    float e = g_asrc[s] + g_adst[d];
    e = e > 0.0f ? e : NEG * e;
    float ex = __expf(e - fdec(g_menc[d]));
    if (lane == 0) atomicAdd(&g_den[d], ex);
    const float* zr = g_z + (size_t)s * HID;
    float*       Sr = g_S + (size_t)d * HID;
    atomicAdd(Sr + lane,      ex * zr[lane]);
    atomicAdd(Sr + 32 + lane, ex * zr[32 + lane]);
}

// ---------------- normalize (+ zero-pad tail to MAXN) --------------------------
__global__ void normalize_embed(const float* __restrict__ gat_b, int N)
{
    int i = blockIdx.x * blockDim.x + threadIdx.x;
    if (i >= MAXN * HID) return;
    if (i < N * HID) {
        int n = i >> 6, f = i & 63;
        g_embed[i] = g_S[i] / g_den[n] + gat_b[f];
    } else {
        g_embed[i] = 0.0f;
    }
}

// ---------------- copy embed into output tail ---------------------------------
__global__ void copy_embed(float* __restrict__ out_embed, int N)
{
    int i = blockIdx.x * blockDim.x + threadIdx.x;
    if (i < N * HID) out_embed[i] = g_embed[i];
}

// ---------------- sim = sigmoid(Z Z^T): f32x2 FMA + symmetric tiles ------------
// 128x128 tile, K=64 single-shot. Upper-triangular blocks only; each block
// writes its tile and (off-diagonal) its transpose, both coalesced.
#define LDP 132                      // padded row length (floats) in smem
#define SIM_SMEM (2 * HID * LDP * 4) // 67584 bytes

__global__ __launch_bounds__(256, 2) void sim_f32x2(float* __restrict__ out, int N)
{
    const int bi = blockIdx.y;       // M tile
    const int bj = blockIdx.x;       // N tile
    if (bi > bj) return;             // symmetry: upper triangle only

    extern __shared__ float sm[];
    float* As = sm;                  // As[k*LDP + r] = Z[i0+r][k]
    float* Bs = sm + HID * LDP;      // Bs[k*LDP + c] = Z[j0+c][k]

    const int tid = threadIdx.x;
    const int i0 = bi * 128;
    const int j0 = bj * 128;

    // ---- cooperative load: 128 rows x 64 floats each side, transposed ----
    {
        const float4* Zi = (const float4*)(g_embed + (size_t)i0 * HID);
        const float4* Zj = (const float4*)(g_embed + (size_t)j0 * HID);
        #pragma unroll
        for (int it = 0; it < 8; it++) {
            int idx = tid + it * 256;        // 0..2047
            int row = idx >> 4;              // 0..127
            int q   = idx & 15;              // float4 index within row
            float4 va = Zi[row * 16 + q];
            float4 vb = Zj[row * 16 + q];
            int k = q * 4;
            As[(k + 0) * LDP + row] = va.x;
            As[(k + 1) * LDP + row] = va.y;
            As[(k + 2) * LDP + row] = va.z;
            As[(k + 3) * LDP + row] = va.w;
            Bs[(k + 0) * LDP + row] = vb.x;
            Bs[(k + 1) * LDP + row] = vb.y;
            Bs[(k + 2) * LDP + row] = vb.z;
            Bs[(k + 3) * LDP + row] = vb.w;
        }
    }
    __syncthreads();

    // ---- mainloop: 8x8 per thread, accumulators as packed f32x2 pairs ----
    const int tx = tid & 15;         // col group: cols tx*8 .. +7
    const int ty = tid >> 4;         // row group: rows ty*8 .. +7
    const int a_off = ty * 8;
    const int b_off = tx * 8;

    ULL acc[8][4];
    #pragma unroll
    for (int r = 0; r < 8; r++)
        #pragma unroll
        for (int c = 0; c < 4; c++) acc[r][c] = 0ULL;

    #pragma unroll 4
    for (int k = 0; k < HID; k++) {
        const float* ar = As + k * LDP + a_off;
        const float* br = Bs + k * LDP + b_off;
        float4 a0 = *(const float4*)ar;
        float4 a1 = *(const float4*)(ar + 4);
        ulonglong2 bq0 = *(const ulonglong2*)br;        // pairs (c0,c1),(c2,c3)
        ulonglong2 bq1 = *(const ulonglong2*)(br + 4);  // pairs (c4,c5),(c6,c7)
        ULL bp0 = bq0.x, bp1 = bq0.y, bp2 = bq1.x, bp3 = bq1.y;
        float av[8] = {a0.x, a0.y, a0.z, a0.w, a1.x, a1.y, a1.z, a1.w};
        #pragma unroll
        for (int r = 0; r < 8; r++) {
            ULL ap;
            PACK_BCAST(ap, av[r]);
            FMA2(acc[r][0], ap, bp0);
            FMA2(acc[r][1], ap, bp1);
            FMA2(acc[r][2], ap, bp2);
            FMA2(acc[r][3], ap, bp3);
        }
    }

    // ---- epilogue: sigmoid + dual write (tile and transpose), 4 rows/half ----
    const bool diag = (bi == bj);
    #pragma unroll
    for (int half = 0; half < 2; half++) {
        float v[4][8];
        #pragma unroll
        for (int r = 0; r < 4; r++)
            #pragma unroll
            for (int cp = 0; cp < 4; cp++) {
                float2 u = unpk(acc[half * 4 + r][cp]);
                v[r][cp * 2 + 0] = sigm(u.x);
                v[r][cp * 2 + 1] = sigm(u.y);
            }

        // normal tile: rows i0+a_off+half*4+r, cols j0+b_off..+7
        #pragma unroll
        for (int r = 0; r < 4; r++) {
            int gi = i0 + a_off + half * 4 + r;
            if (gi >= N) continue;
            int gj = j0 + b_off;
            float* orow = out + (size_t)gi * N + gj;
            if (gj + 7 < N) {
                *(float4*)orow       = make_float4(v[r][0], v[r][1], v[r][2], v[r][3]);
                *(float4*)(orow + 4) = make_float4(v[r][4], v[r][5], v[r][6], v[r][7]);
            } else {
                #pragma unroll
                for (int c = 0; c < 8; c++)
                    if (gj + c < N) orow[c] = v[r][c];
            }
        }

        // transposed tile: rows j0+b_off+c, cols i0+a_off+half*4..+3
        if (!diag) {
            #pragma unroll
            for (int c = 0; c < 8; c++) {
                int gi = j0 + b_off + c;
                if (gi >= N) continue;
                int gj = i0 + a_off + half * 4;
                float* orow = out + (size_t)gi * N + gj;
                if (gj + 3 < N) {
                    *(float4*)orow = make_float4(v[0][c], v[1][c], v[2][c], v[3][c]);
                } else {
                    #pragma unroll
                    for (int r = 0; r < 4; r++)
                        if (gj + r < N) orow[r] = v[r][c];
                }
            }
        }
    }
}

// ---------------- launch --------------------------------------------------------
extern "C" void kernel_launch(void* const* d_in, const int* in_sizes, int n_in,
                              void* d_out, int out_size)
{
    const float* x    = (const float*)d_in[0];
    const void*  ei   = d_in[1];
    const float* W1   = (const float*)d_in[2];
    const float* b1   = (const float*)d_in[3];
    const float* W2   = (const float*)d_in[4];
    const float* atts = (const float*)d_in[5];
    const float* attd = (const float*)d_in[6];
    const float* gb   = (const float*)d_in[7];

    const int N = in_sizes[0] / IN_DIM;
    const int E = in_sizes[1] / 2;
    const int ET = E + N;

    float* out = (float*)d_out;

    detect_dtype<<<1, 1>>>(ei, N);
    init_scratch<<<(N * HID + 255) / 256, 256>>>(N);
    node_fwd<<<(N + 31) / 32, 256>>>(x, W1, b1, W2, atts, attd, N);
    edge_max<<<(ET + 255) / 256, 256>>>(ei, E, N);
    edge_scatter<<<(ET * 32 + 255) / 256, 256>>>(ei, E, N);
    normalize_embed<<<(MAXN * HID + 255) / 256, 256>>>(gb, N);

    if ((size_t)out_size >= (size_t)N * N + (size_t)N * HID) {
        copy_embed<<<(N * HID + 255) / 256, 256>>>(out + (size_t)N * N, N);
    }

    static int smem_set = 0;
    if (!smem_set) {
        cudaFuncSetAttribute(sim_f32x2, cudaFuncAttributeMaxDynamicSharedMemorySize,
                             SIM_SMEM);
        smem_set = 1;
    }
    const int nt = (N + 127) / 128;
    dim3 grid(nt, nt);
    sim_f32x2<<<grid, 256, SIM_SMEM>>>(out, N);
}